// round 8
// baseline (speedup 1.0000x reference)
#include <cuda_runtime.h>
#include <math.h>

// Problem constants
#define BB   8
#define TT   2048
#define DIN  512
#define DD   1024
#define MTOT (BB*TT)        // 16384
#define LN_EPS 1e-5f

typedef unsigned long long ull;

// Scratch (static __device__ arrays: no runtime allocation)
__device__ float g_ab[(size_t)MTOT * DD * 2];  // interleaved (a,b) pairs
__device__ float g_h[(size_t)MTOT * DD];       // h_post

// ---------------------------------------------------------------------------
// Packed f32x2 helpers. Each lane is an independent IEEE fp32 rn FMA, so the
// per-element accumulation chain is bit-identical to scalar fmaf.
// ---------------------------------------------------------------------------
__device__ __forceinline__ ull pk2(float lo, float hi) {
    ull r; asm("mov.b64 %0, {%1, %2};" : "=l"(r) : "f"(lo), "f"(hi)); return r;
}
__device__ __forceinline__ float2 up2(ull v) {
    float2 f; asm("mov.b64 {%0, %1}, %2;" : "=f"(f.x), "=f"(f.y) : "l"(v)); return f;
}
__device__ __forceinline__ ull fma2(ull a, ull b, ull c) {
#if defined(__CUDA_ARCH__) && (__CUDA_ARCH__ >= 1000)
    ull d;
    asm("fma.rn.f32x2 %0, %1, %2, %3;" : "=l"(d) : "l"(a), "l"(b), "l"(c));
    return d;
#else
    float2 af = up2(a), bf = up2(b), cf = up2(c);
    return pk2(fmaf(af.x, bf.x, cf.x), fmaf(af.y, bf.y, cf.y));
#endif
}

__device__ __forceinline__ unsigned smem_addr_u32(const void* p) {
    unsigned a;
    asm("{ .reg .u64 t; cvta.to.shared.u64 t, %1; cvt.u32.u64 %0, t; }" : "=r"(a) : "l"(p));
    return a;
}
__device__ __forceinline__ void cp16(unsigned dst, const void* src) {
    asm volatile("cp.async.cg.shared.global [%0], [%1], 16;" :: "r"(dst), "l"(src));
}
__device__ __forceinline__ void cp_commit() {
    asm volatile("cp.async.commit_group;" ::: "memory");
}
__device__ __forceinline__ void cp_wait1() {
    asm volatile("cp.async.wait_group 1;" ::: "memory");
}

// ---------------------------------------------------------------------------
// Kernel 1: dual GEMM (x@Wd, x@Wb) + fused discretization epilogue.
// CRITICAL: each output element is ONE sequential-k fp32 FMA chain
// (k = 0..511 ascending) — bit-matches the reference SGEMM so the chaotic
// spike threshold decisions stay identical. Do NOT reorder.
// CTA tile 128(M) x 64(N) for BOTH matrices, 256 threads, occ 2.
// Per-thread 8m x 4n per matrix (32 f32x2 accs = 64 regs).
// 3-stage cp.async ring, one barrier per k-tile, empty commits in the tail.
// ---------------------------------------------------------------------------
#define BM 128
#define BN 64
#define BK 16
#define KT (DIN / BK)   // 32
#define STG 3

__global__ __launch_bounds__(256, 2)
void gemm_epi_kernel(const float* __restrict__ x,
                     const float* __restrict__ Wd,
                     const float* __restrict__ bd,
                     const float* __restrict__ Wb,
                     const float* __restrict__ bb,
                     const float* __restrict__ A_log)
{
    __shared__ float As[STG][BM][BK];       // x tile, [m][k], 8KB/stage
    __shared__ float Ws[STG][2][BK][BN];    // [mat][k][n],   8KB/stage

    const int tid = threadIdx.x;
    const int m0  = blockIdx.y * BM;
    const int n0  = blockIdx.x * BN;

    // compute mapping (round-6 proven shape)
    const int tm = (tid >> 4) * 8;     // m offset (two groups of 16 lanes)
    const int tn = (tid & 15) * 4;     // n offset

    // cp.async staging mapping
    // A: 128 rows x 64B = 512 chunks; thread does chunks tid and tid+256
    const int a_r0 = tid >> 2;               // row for chunk tid
    const int a_c0 = (tid & 3) * 4;          // k offset
    // W: 16 rows x 256B = 256 chunks per matrix; thread does chunk tid (tid<256)
    const int w_r = tid >> 4;                 // k row
    const int w_c = (tid & 15) * 4;           // n offset

    const float* xrow0 = x + (size_t)(m0 + a_r0)       * DIN + a_c0;
    const float* xrow1 = x + (size_t)(m0 + (a_r0 | 64)) * DIN + a_c0;
    const float* wdrow = Wd + (size_t)w_r * DD + n0 + w_c;
    const float* wbrow = Wb + (size_t)w_r * DD + n0 + w_c;

    ull accd[8][2], accb[8][2];
    #pragma unroll
    for (int i = 0; i < 8; i++) {
        accd[i][0] = accd[i][1] = 0ull;
        accb[i][0] = accb[i][1] = 0ull;
    }

    // issue one k-tile's loads into stage s
    auto issue = [&](int kt, int s) {
        const int ko = kt * BK;
        cp16(smem_addr_u32(&As[s][a_r0][a_c0]),      xrow0 + ko);
        cp16(smem_addr_u32(&As[s][a_r0 | 64][a_c0]), xrow1 + ko);
        cp16(smem_addr_u32(&Ws[s][0][w_r][w_c]), wdrow + (size_t)ko * DD);
        cp16(smem_addr_u32(&Ws[s][1][w_r][w_c]), wbrow + (size_t)ko * DD);
    };

    // prologue: stages 0..STG-2
    issue(0, 0); cp_commit();
    issue(1, 1); cp_commit();

    for (int kt = 0; kt < KT; ++kt) {
        const int s = kt % STG;
        cp_wait1();            // groups 1..(kt+1) done -> tile kt resident
        __syncthreads();

        // compute k = kt*16 .. kt*16+15, ascending (4 groups of 4)
        #pragma unroll
        for (int kq = 0; kq < 4; ++kq) {
            float4 am4[8];
            #pragma unroll
            for (int i = 0; i < 8; i++)
                am4[i] = *(const float4*)&As[s][tm + i][kq * 4];
            #pragma unroll
            for (int j = 0; j < 4; ++j) {
                const int kk = kq * 4 + j;
                ulonglong2 wdp = *(const ulonglong2*)&Ws[s][0][kk][tn];
                ulonglong2 wbp = *(const ulonglong2*)&Ws[s][1][kk][tn];
                #pragma unroll
                for (int i = 0; i < 8; i++) {
                    float a = (&am4[i].x)[j];
                    ull aa = pk2(a, a);
                    accd[i][0] = fma2(aa, wdp.x, accd[i][0]);
                    accd[i][1] = fma2(aa, wdp.y, accd[i][1]);
                    accb[i][0] = fma2(aa, wbp.x, accb[i][0]);
                    accb[i][1] = fma2(aa, wbp.y, accb[i][1]);
                }
            }
        }

        // issue tile kt+2 into its stage (buffer freed at iter kt-1, all warps
        // passed this iter's barrier). Empty commit keeps group counting sane.
        if (kt + STG - 1 < KT) issue(kt + STG - 1, (kt + STG - 1) % STG);
        cp_commit();
    }

    // Epilogue: delta = softplus(yd + bd); b_step = delta*(yb + bb);
    //           a_step = exp(-delta * exp(A_log)); store interleaved (a,b).
    const int n = n0 + tn;
    float4 bd4 = *(const float4*)&bd[n];
    float4 bb4 = *(const float4*)&bb[n];
    float4 al4 = *(const float4*)&A_log[n];
    float Av[4] = {expf(al4.x), expf(al4.y), expf(al4.z), expf(al4.w)};
    float bdv4[4] = {bd4.x, bd4.y, bd4.z, bd4.w};
    float bbv4[4] = {bb4.x, bb4.y, bb4.z, bb4.w};

    #pragma unroll
    for (int i = 0; i < 8; i++) {
        const int m = m0 + tm + i;
        float2 d01 = up2(accd[i][0]), d23 = up2(accd[i][1]);
        float2 b01 = up2(accb[i][0]), b23 = up2(accb[i][1]);
        float yd[4] = {d01.x, d01.y, d23.x, d23.y};
        float yb[4] = {b01.x, b01.y, b23.x, b23.y};
        float ao[4], bo[4];
        #pragma unroll
        for (int j = 0; j < 4; j++) {
            float zd = yd[j] + bdv4[j];
            float sp = fmaxf(zd, 0.f) + log1pf(expf(-fabsf(zd)));
            bo[j] = sp * (yb[j] + bbv4[j]);
            ao[j] = expf(-sp * Av[j]);
        }
        float4 p0, p1;
        p0.x = ao[0]; p0.y = bo[0]; p0.z = ao[1]; p0.w = bo[1];
        p1.x = ao[2]; p1.y = bo[2]; p1.z = ao[3]; p1.w = bo[3];
        float* dst = g_ab + (size_t)m * (2 * DD) + 2 * n;
        *(float4*)dst = p0;
        *(float4*)(dst + 4) = p1;
    }
}

// ---------------------------------------------------------------------------
// Kernel 2: sequential spiking scan. 8192 lanes, 256 blocks x 32 threads
// (covers all SMs). LDG.64 interleaved (a,b); fmaf chain identical.
// ---------------------------------------------------------------------------
#define SU 32

__global__ __launch_bounds__(32)
void scan_kernel(const float* __restrict__ thr, float* __restrict__ spikes)
{
    const int gid = blockIdx.x * 32 + threadIdx.x;   // 0..8191
    const int b = gid >> 10;
    const int d = gid & (DD - 1);

    const float2* abp = (const float2*)g_ab + (size_t)b * TT * DD + d;
    float* hp = g_h    + (size_t)b * TT * DD + d;
    float* sp = spikes + (size_t)b * TT * DD + d;

    const float th = thr[d];
    float h = 0.f;

    for (int t = 0; t < TT; t += SU) {
        float2 ab[SU];
        #pragma unroll
        for (int j = 0; j < SU; j++) ab[j] = abp[(size_t)(t + j) * DD];

        #pragma unroll
        for (int j = 0; j < SU; j++) {
            h = fmaf(ab[j].x, h, ab[j].y);
            float s = (h - th > 0.f) ? 1.f : 0.f;
            if (s > 0.f) h = 0.f;
            hp[(size_t)(t + j) * DD] = h;
            sp[(size_t)(t + j) * DD] = s;
        }
    }
}

// ---------------------------------------------------------------------------
// Kernel 3: LayerNorm over D=1024, one CTA (256 threads x float4) per row.
// ---------------------------------------------------------------------------
__global__ __launch_bounds__(256)
void ln_kernel(const float* __restrict__ gamma, const float* __restrict__ beta,
               float* __restrict__ out)
{
    const int row = blockIdx.x;
    const int tid = threadIdx.x;
    const int lane = tid & 31, wid = tid >> 5;
    const float* hrow = g_h + (size_t)row * DD;

    __shared__ float red[8];

    float4 v = *(const float4*)&hrow[tid * 4];
    float s = v.x + v.y + v.z + v.w;
    #pragma unroll
    for (int o = 16; o > 0; o >>= 1) s += __shfl_xor_sync(0xffffffffu, s, o);
    if (lane == 0) red[wid] = s;
    __syncthreads();
    float tot = 0.f;
    #pragma unroll
    for (int i = 0; i < 8; i++) tot += red[i];
    const float mu = tot * (1.0f / (float)DD);

    float dx0 = v.x - mu, dx1 = v.y - mu, dx2 = v.z - mu, dx3 = v.w - mu;
    float ss = dx0 * dx0 + dx1 * dx1 + dx2 * dx2 + dx3 * dx3;
    __syncthreads();   // protect red[] reuse
    #pragma unroll
    for (int o = 16; o > 0; o >>= 1) ss += __shfl_xor_sync(0xffffffffu, ss, o);
    if (lane == 0) red[wid] = ss;
    __syncthreads();
    float tot2 = 0.f;
    #pragma unroll
    for (int i = 0; i < 8; i++) tot2 += red[i];
    const float rstd = rsqrtf(tot2 * (1.0f / (float)DD) + LN_EPS);

    float4 g = *(const float4*)&gamma[tid * 4];
    float4 bt = *(const float4*)&beta[tid * 4];
    float4 o4;
    o4.x = dx0 * rstd * g.x + bt.x;
    o4.y = dx1 * rstd * g.y + bt.y;
    o4.z = dx2 * rstd * g.z + bt.z;
    o4.w = dx3 * rstd * g.w + bt.w;
    *(float4*)&out[(size_t)row * DD + tid * 4] = o4;
}

// ---------------------------------------------------------------------------
extern "C" void kernel_launch(void* const* d_in, const int* in_sizes, int n_in,
                              void* d_out, int out_size)
{
    const float* x     = (const float*)d_in[0];
    const float* Wd    = (const float*)d_in[1];
    const float* bd    = (const float*)d_in[2];
    const float* Wb    = (const float*)d_in[3];
    const float* bb    = (const float*)d_in[4];
    const float* A_log = (const float*)d_in[5];
    const float* thr   = (const float*)d_in[6];
    const float* gamma = (const float*)d_in[7];
    const float* beta  = (const float*)d_in[8];

    float* out    = (float*)d_out;
    float* spikes = out + (size_t)MTOT * DD;   // tuple (out, spikes) concatenated

    dim3 ggrid(DD / BN, MTOT / BM);            // (16, 128) = 2048 CTAs
    gemm_epi_kernel<<<ggrid, 256>>>(x, Wd, bd, Wb, bb, A_log);

    scan_kernel<<<(BB * DD) / 32, 32>>>(thr, spikes);   // 256 CTAs x 32

    ln_kernel<<<MTOT, 256>>>(gamma, beta, out);         // 16384 CTAs
}